// round 2
// baseline (speedup 1.0000x reference)
#include <cuda_runtime.h>

#define SEQ    512
#define BATCH  128
#define INPUT  128
#define HIDDEN 512

// double-buffered hidden state (no allocations allowed)
__device__ float g_hbuf[2][BATCH * HIDDEN];

// ---------------------------------------------------------------------------
// zero-init buffer 0 of the hidden state (h0 = 0)
// ---------------------------------------------------------------------------
__global__ void zero_h0_kernel()
{
    int i = blockIdx.x * blockDim.x + threadIdx.x;
    if (i < BATCH * HIDDEN) g_hbuf[0][i] = 0.0f;
}

// ---------------------------------------------------------------------------
// Phase 1: proj[row, n] = sum_k input[row, k] * W_in[n, k]
//   row = s*BATCH + b  (65536 rows), k in [0,128), n in [0,512)
//   written directly into d_out[row*HIDDEN + n] (later overwritten by h states)
// Tiling: 64x64 output tile per CTA, K chunked by 64, 256 threads, 4x4/thread.
// ---------------------------------------------------------------------------
__global__ __launch_bounds__(256) void proj_kernel(
    const float* __restrict__ A,   // (65536, 128)
    const float* __restrict__ W,   // (512, 128)
    float* __restrict__ C)         // (65536, 512)
{
    __shared__ float As[64][65];   // [k][row]  (pad 65: conflict-free stores)
    __shared__ float Bs[64][65];   // [k][n]

    const int tid  = threadIdx.x;
    const int tx   = tid & 15;     // n group
    const int ty   = tid >> 4;     // m group
    const int row0 = blockIdx.x * 64;
    const int n0   = blockIdx.y * 64;

    float acc[4][4] = {};

    for (int k0 = 0; k0 < INPUT; k0 += 64) {
        // load 64x64 chunks of A and W (coalesced along k)
        #pragma unroll
        for (int i = 0; i < 16; i++) {
            int e  = tid + i * 256;
            int r  = e >> 6;
            int kk = e & 63;
            As[kk][r] = A[(row0 + r) * INPUT + k0 + kk];
            Bs[kk][r] = W[(n0 + r) * INPUT + k0 + kk];
        }
        __syncthreads();

        #pragma unroll 8
        for (int k = 0; k < 64; k++) {
            float a[4], b[4];
            #pragma unroll
            for (int i = 0; i < 4; i++) a[i] = As[k][ty * 4 + i];
            #pragma unroll
            for (int j = 0; j < 4; j++) b[j] = Bs[k][tx * 4 + j];
            #pragma unroll
            for (int i = 0; i < 4; i++)
                #pragma unroll
                for (int j = 0; j < 4; j++)
                    acc[i][j] += a[i] * b[j];
        }
        __syncthreads();
    }

    #pragma unroll
    for (int i = 0; i < 4; i++) {
        int row = row0 + ty * 4 + i;
        #pragma unroll
        for (int j = 0; j < 4; j++)
            C[row * HIDDEN + n0 + tx * 4 + j] = acc[i][j];
    }
}

// ---------------------------------------------------------------------------
// Phase 2 step kernel: one time step.
//   hidden_out[b, n] = sum_k relu(h_prev[b, k]) * W_hid[n, k]
//   h_new = 0.5*h_prev + 0.5*(hidden_out + proj[s,b,n] + noise[s,n])
//   writes h_new into g_hbuf[cur^1] and d_out[s,b,n] (overwriting proj)
// Grid: (16 n-tiles, 8 b-tiles), 128 threads, tile 16(b) x 32(n), 2x2/thread.
// smem: Hs[512][17] relu(h) tile + Ws[512][33] W_hid slice = 102400 B dynamic.
// ---------------------------------------------------------------------------
#define STEP_SMEM_BYTES ((512 * 17 + 512 * 33) * 4)

__global__ __launch_bounds__(128) void step_kernel(
    int cur,                               // which h buffer holds h_prev
    const float* __restrict__ Whid,        // (512, 512)
    const float* __restrict__ noise_s,     // (512,) for this step
    float* __restrict__ out_s)             // d_out + s*BATCH*HIDDEN: proj in, h out
{
    extern __shared__ float sm[];
    float* Hs = sm;                 // [k][m], stride 17
    float* Ws = sm + 512 * 17;      // [k][n], stride 33

    const float* hprev = g_hbuf[cur];
    float*       hnext = g_hbuf[cur ^ 1];

    const int tid = threadIdx.x;
    const int n0  = blockIdx.x * 32;
    const int b0  = blockIdx.y * 16;

    // load relu(h_prev) tile: 16 rows x 512 k (vectorized float4)
    #pragma unroll
    for (int i = 0; i < 16; i++) {
        int e  = tid + i * 128;        // 2048 float4s
        int m  = e >> 7;
        int kq = e & 127;
        float4 v = reinterpret_cast<const float4*>(hprev)[(b0 + m) * 128 + kq];
        Hs[(4 * kq + 0) * 17 + m] = fmaxf(v.x, 0.0f);
        Hs[(4 * kq + 1) * 17 + m] = fmaxf(v.y, 0.0f);
        Hs[(4 * kq + 2) * 17 + m] = fmaxf(v.z, 0.0f);
        Hs[(4 * kq + 3) * 17 + m] = fmaxf(v.w, 0.0f);
    }
    // load W_hid slice: 32 rows x 512 k
    #pragma unroll
    for (int i = 0; i < 32; i++) {
        int e  = tid + i * 128;        // 4096 float4s
        int n  = e >> 7;
        int kq = e & 127;
        float4 v = reinterpret_cast<const float4*>(Whid)[(n0 + n) * 128 + kq];
        Ws[(4 * kq + 0) * 33 + n] = v.x;
        Ws[(4 * kq + 1) * 33 + n] = v.y;
        Ws[(4 * kq + 2) * 33 + n] = v.z;
        Ws[(4 * kq + 3) * 33 + n] = v.w;
    }
    __syncthreads();

    const int tx  = tid & 15;      // n group
    const int ty  = tid >> 4;      // m group (0..7)
    const int m0  = ty * 2;
    const int nn0 = tx * 2;

    float acc00 = 0.f, acc01 = 0.f, acc10 = 0.f, acc11 = 0.f;

    #pragma unroll 8
    for (int k = 0; k < HIDDEN; k++) {
        float h0v = Hs[k * 17 + m0];
        float h1v = Hs[k * 17 + m0 + 1];
        float w0  = Ws[k * 33 + nn0];
        float w1  = Ws[k * 33 + nn0 + 1];
        acc00 += h0v * w0;  acc01 += h0v * w1;
        acc10 += h1v * w0;  acc11 += h1v * w1;
    }

    #pragma unroll
    for (int i = 0; i < 2; i++) {
        #pragma unroll
        for (int j = 0; j < 2; j++) {
            float a = (i == 0) ? ((j == 0) ? acc00 : acc01)
                               : ((j == 0) ? acc10 : acc11);
            int b   = b0 + m0 + i;
            int n   = n0 + nn0 + j;
            int idx = b * HIDDEN + n;
            float x  = out_s[idx];       // proj (read before overwrite)
            float hp = hprev[idx];
            float hn = 0.5f * hp + 0.5f * (a + x + noise_s[n]);
            hnext[idx] = hn;
            out_s[idx] = hn;
        }
    }
}

// ---------------------------------------------------------------------------
// copy final hidden state to the tail of d_out (tuple: (output, hidden))
// ---------------------------------------------------------------------------
__global__ void tail_copy_kernel(float* __restrict__ out)
{
    int i = blockIdx.x * blockDim.x + threadIdx.x;
    if (i < BATCH * HIDDEN)
        out[(size_t)SEQ * BATCH * HIDDEN + i] =
            out[(size_t)(SEQ - 1) * BATCH * HIDDEN + i];
}

// ---------------------------------------------------------------------------
extern "C" void kernel_launch(void* const* d_in, const int* in_sizes, int n_in,
                              void* d_out, int out_size)
{
    const float* input = (const float*)d_in[0];   // (512,128,128)
    const float* W_in  = (const float*)d_in[1];   // (512,128)
    const float* W_hid = (const float*)d_in[2];   // (512,512)
    const float* noise = (const float*)d_in[3];   // (512,512)
    float* out = (float*)d_out;

    cudaFuncSetAttribute(step_kernel,
                         cudaFuncAttributeMaxDynamicSharedMemorySize,
                         STEP_SMEM_BYTES);

    // h0 = 0
    zero_h0_kernel<<<(BATCH * HIDDEN + 255) / 256, 256>>>();

    // Phase 1: input projection into d_out
    {
        dim3 grid((SEQ * BATCH) / 64, HIDDEN / 64);
        proj_kernel<<<grid, 256>>>(input, W_in, out);
    }

    // Phase 2: 512 sequential steps
    {
        dim3 grid(HIDDEN / 32, BATCH / 16);
        for (int s = 0; s < SEQ; s++) {
            step_kernel<<<grid, 128, STEP_SMEM_BYTES>>>(
                s & 1, W_hid, noise + (size_t)s * HIDDEN,
                out + (size_t)s * BATCH * HIDDEN);
        }
    }

    // final hidden state tail (if present in the output buffer)
    if (out_size >= SEQ * BATCH * HIDDEN + BATCH * HIDDEN) {
        tail_copy_kernel<<<(BATCH * HIDDEN + 255) / 256, 256>>>(out);
    }
}

// round 3
// speedup vs baseline: 1.0574x; 1.0574x over previous
#include <cuda_runtime.h>
#include <cstdint>

#define SEQ    512
#define BATCH  128
#define INPUT  128
#define HIDDEN 512

#define CLUSTER  8
#define NCHUNK   64      // HIDDEN / CLUSTER
#define BCHUNK   8       // batch rows per cluster
#define THREADS  256
#define WS_STRIDE 65     // padded k-row stride for W slice

// dynamic smem: W slice [512][65] + h double buffer [2][512][8]
#define SMEM_FLOATS (512 * WS_STRIDE + 2 * 512 * 8)
#define SMEM_BYTES  (SMEM_FLOATS * 4)

// ---------------------------------------------------------------------------
// Phase 1: proj[row, n] = sum_k input[row, k] * W_in[n, k]  -> written to d_out
// ---------------------------------------------------------------------------
__global__ __launch_bounds__(256) void proj_kernel(
    const float* __restrict__ A,   // (65536, 128)
    const float* __restrict__ W,   // (512, 128)
    float* __restrict__ C)         // (65536, 512)
{
    __shared__ float As[64][65];
    __shared__ float Bs[64][65];

    const int tid  = threadIdx.x;
    const int tx   = tid & 15;
    const int ty   = tid >> 4;
    const int row0 = blockIdx.x * 64;
    const int n0   = blockIdx.y * 64;

    float acc[4][4] = {};

    for (int k0 = 0; k0 < INPUT; k0 += 64) {
        #pragma unroll
        for (int i = 0; i < 16; i++) {
            int e  = tid + i * 256;
            int r  = e >> 6;
            int kk = e & 63;
            As[kk][r] = A[(row0 + r) * INPUT + k0 + kk];
            Bs[kk][r] = W[(n0 + r) * INPUT + k0 + kk];
        }
        __syncthreads();

        #pragma unroll 8
        for (int k = 0; k < 64; k++) {
            float a[4], b[4];
            #pragma unroll
            for (int i = 0; i < 4; i++) a[i] = As[k][ty * 4 + i];
            #pragma unroll
            for (int j = 0; j < 4; j++) b[j] = Bs[k][tx * 4 + j];
            #pragma unroll
            for (int i = 0; i < 4; i++)
                #pragma unroll
                for (int j = 0; j < 4; j++)
                    acc[i][j] += a[i] * b[j];
        }
        __syncthreads();
    }

    #pragma unroll
    for (int i = 0; i < 4; i++) {
        int row = row0 + ty * 4 + i;
        #pragma unroll
        for (int j = 0; j < 4; j++)
            C[row * HIDDEN + n0 + tx * 4 + j] = acc[i][j];
    }
}

// ---------------------------------------------------------------------------
// Phase 2: persistent cluster kernel. 16 clusters x 8 CTAs. One CTA per SM.
//   cluster c: batch rows [8c, 8c+8); rank r: hidden cols [64r, 64r+64)
//   W slice resident in smem for all 512 steps. relu(h) exchanged via DSMEM
//   multicast stores + one barrier.cluster per step (double-buffered).
// ---------------------------------------------------------------------------
__global__ void __launch_bounds__(THREADS, 1) __cluster_dims__(CLUSTER, 1, 1)
recurrent_kernel(const float* __restrict__ Whid,     // (512, 512)
                 const float* __restrict__ noise,    // (512, 512)
                 float* __restrict__ out)            // (512, 128, 512): proj in, h out
{
    extern __shared__ float sm[];
    float* Ws = sm;                        // [k * 65 + n]
    float* hs = sm + 512 * WS_STRIDE;      // [pp*4096 + k*8 + b]   (relu'd h)

    const int tid = threadIdx.x;
    uint32_t rank;
    asm("mov.u32 %0, %%cluster_ctarank;" : "=r"(rank));
    const int n0    = (int)rank * NCHUNK;
    const int bbase = (blockIdx.x >> 3) * BCHUNK;

    // ---- load W_hid slice (coalesced global read, transposed into smem) ----
    for (int e = tid; e < NCHUNK * 128; e += THREADS) {
        int n  = e >> 7;        // 0..63
        int kq = e & 127;       // float4 index along k
        float4 v = reinterpret_cast<const float4*>(Whid)[(n0 + n) * 128 + kq];
        Ws[(4 * kq + 0) * WS_STRIDE + n] = v.x;
        Ws[(4 * kq + 1) * WS_STRIDE + n] = v.y;
        Ws[(4 * kq + 2) * WS_STRIDE + n] = v.z;
        Ws[(4 * kq + 3) * WS_STRIDE + n] = v.w;
    }
    // ---- zero both h buffers (h0 = 0 -> relu(h0) = 0) ----
    for (int e = tid; e < 2 * 512 * 8; e += THREADS) hs[e] = 0.0f;

    // ---- peer smem addresses for the h buffers ----
    uint32_t hs_addr;
    asm("{ .reg .u64 t; cvta.to.shared.u64 t, %1; cvt.u32.u64 %0, t; }"
        : "=r"(hs_addr) : "l"(hs));
    uint32_t peer[CLUSTER];
    #pragma unroll
    for (int r = 0; r < CLUSTER; r++)
        asm("mapa.shared::cluster.u32 %0, %1, %2;"
            : "=r"(peer[r]) : "r"(hs_addr), "r"(r));

    __syncthreads();
    asm volatile("barrier.cluster.arrive.aligned;" ::: "memory");
    asm volatile("barrier.cluster.wait.aligned;"   ::: "memory");

    // ---- thread -> (batch pair, n) mapping ----
    // warp covers 2 consecutive batch-pairs x 16 n (W reads dedup in-warp)
    const int warp = tid >> 5, lane = tid & 31;
    const int bp   = 2 * (warp & 1) + (lane >> 4);    // 0..3
    const int n    = (warp >> 1) * 16 + (lane & 15);  // 0..63
    const int col  = n0 + n;                          // global hidden index
    const int bglb = bbase + 2 * bp;                  // global batch row (even)

    float rh0 = 0.0f, rh1 = 0.0f;   // raw (pre-relu) hidden state, in registers
    int pp = 0;

    for (int s = 0; s < SEQ; s++) {
        // prefetch proj + noise early (latency hidden by the matvec)
        float* o  = out + ((size_t)s * BATCH + bglb) * HIDDEN + col;
        float x0  = o[0];
        float x1  = o[HIDDEN];
        float nz  = __ldg(&noise[s * HIDDEN + col]);

        const float* hp = hs + pp * 4096 + 2 * bp;
        float acc0 = 0.0f, acc1 = 0.0f;
        #pragma unroll 16
        for (int k = 0; k < HIDDEN; k++) {
            float  w  = Ws[k * WS_STRIDE + n];
            float2 h2 = *reinterpret_cast<const float2*>(hp + k * 8);
            acc0 = fmaf(h2.x, w, acc0);
            acc1 = fmaf(h2.y, w, acc1);
        }

        float hn0 = 0.5f * rh0 + 0.5f * (acc0 + x0 + nz);
        float hn1 = 0.5f * rh1 + 0.5f * (acc1 + x1 + nz);
        rh0 = hn0; rh1 = hn1;
        o[0]      = hn0;          // overwrite proj with hidden state
        o[HIDDEN] = hn1;

        // multicast relu(h_new) chunk into every cluster CTA's next buffer
        float r0 = fmaxf(hn0, 0.0f), r1 = fmaxf(hn1, 0.0f);
        uint32_t off = (uint32_t)(((pp ^ 1) * 4096 + col * 8 + 2 * bp) * 4);
        #pragma unroll
        for (int r = 0; r < CLUSTER; r++)
            asm volatile("st.shared::cluster.v2.f32 [%0], {%1, %2};"
                         :: "r"(peer[r] + off), "f"(r0), "f"(r1) : "memory");

        asm volatile("barrier.cluster.arrive.aligned;" ::: "memory");
        asm volatile("barrier.cluster.wait.aligned;"   ::: "memory");
        pp ^= 1;
    }
}

// ---------------------------------------------------------------------------
// final hidden state tail (tuple output: (output, hidden))
// ---------------------------------------------------------------------------
__global__ void tail_copy_kernel(float* __restrict__ out)
{
    int i = blockIdx.x * blockDim.x + threadIdx.x;
    if (i < BATCH * HIDDEN)
        out[(size_t)SEQ * BATCH * HIDDEN + i] =
            out[(size_t)(SEQ - 1) * BATCH * HIDDEN + i];
}

// ---------------------------------------------------------------------------
extern "C" void kernel_launch(void* const* d_in, const int* in_sizes, int n_in,
                              void* d_out, int out_size)
{
    const float* input = (const float*)d_in[0];   // (512,128,128)
    const float* W_in  = (const float*)d_in[1];   // (512,128)
    const float* W_hid = (const float*)d_in[2];   // (512,512)
    const float* noise = (const float*)d_in[3];   // (512,512)
    float* out = (float*)d_out;

    cudaFuncSetAttribute(recurrent_kernel,
                         cudaFuncAttributeMaxDynamicSharedMemorySize,
                         SMEM_BYTES);

    // Phase 1: input projection into d_out
    {
        dim3 grid((SEQ * BATCH) / 64, HIDDEN / 64);
        proj_kernel<<<grid, 256>>>(input, W_in, out);
    }

    // Phase 2: persistent recurrence (128 CTAs = 16 clusters of 8)
    recurrent_kernel<<<128, THREADS, SMEM_BYTES>>>(W_hid, noise, out);

    // final hidden state tail
    if (out_size >= SEQ * BATCH * HIDDEN + BATCH * HIDDEN) {
        tail_copy_kernel<<<(BATCH * HIDDEN + 255) / 256, 256>>>(out);
    }
}